// round 10
// baseline (speedup 1.0000x reference)
#include <cuda_runtime.h>
#include <cuda_bf16.h>
#include <cstdint>

#define B_MAX 16384

// ---------------- persistent scratch (__device__ globals; no allocations) ----
__device__ unsigned long long g_w2P[1024 * 32]; // packed biased fixed-point:
                                                //   low  = rn(w2[2l][h]*2^22)+2^21
                                                //   high = rn(w2[2l+1][h]*2^22)+2^21
__device__ float g_nnw2T[1024 * 64];  // nn_w2 transposed: [h][o]
__device__ float g_fcT[1600 * 256];   // cnn_fc_w transposed: [k][o]
__device__ float g_combT[384 * 64];   // comb_w transposed: [c][o]
__device__ float g_snn[B_MAX * 64];
__device__ float g_nn[B_MAX * 64];
__device__ float g_cnn[B_MAX * 256];

#define W2_SCALE    4194304.0f        // 2^22
#define W2_INVSCALE 2.3841858e-7f     // 2^-22
#define W2_BIAS     2097152u          // 2^21

// ---------------- weight transpose / packing ---------------------------------
__global__ void prep_kernel(const float* __restrict__ snn_w2,
                            const float* __restrict__ nn_w2,
                            const float* __restrict__ fc_w,
                            const float* __restrict__ comb_w) {
    int i = blockIdx.x * blockDim.x + threadIdx.x;
    if (i < 1024 * 32) {
        int h = i >> 5, l = i & 31;
        unsigned ex = (unsigned)(__float2int_rn(snn_w2[(2 * l) * 1024 + h] * W2_SCALE)) + W2_BIAS;
        unsigned ey = (unsigned)(__float2int_rn(snn_w2[(2 * l + 1) * 1024 + h] * W2_SCALE)) + W2_BIAS;
        g_w2P[i] = ((unsigned long long)ey << 32) | (unsigned long long)ex;
    }
    if (i < 1024 * 64) {
        int h = i >> 6, o = i & 63;
        g_nnw2T[i] = nn_w2[o * 1024 + h];
    }
    if (i < 1600 * 256) {
        int k = i >> 8, o = i & 255;
        g_fcT[i] = fc_w[o * 1600 + k];
    }
    if (i < 384 * 64) {
        int c = i >> 6, o = i & 63;
        g_combT[i] = comb_w[o * 384 + c];
    }
}

// ---------------- SNN: one block (1024 thr) per batch row --------------------
// Active-neuron compaction (drive c <= ~0.05 provably never spikes: mem
// asymptote 20c <= 1). Phase 1: each active neuron's thread builds its 100-bit
// spike train in registers; warp ballots also record per-chunk masks (for the
// per-timestep spike counts K_t). Phase 2 (neuron-major): one packed 64-bit
// shared atomicAdd per spike covers BOTH outputs of the owning lane; biased
// encoding guarantees no low->high carry, so the sum is exact fixed point and
// order-independent (deterministic). Phase 3 decodes with K_t and runs the
// layer-2 LIF scan.
__global__ __launch_bounds__(1024, 2) void snn_kernel(const float* __restrict__ x,
                                                      const float* __restrict__ w1,
                                                      const float* __restrict__ b1,
                                                      const float* __restrict__ b2,
                                                      int B) {
    __shared__ unsigned long long s_acc[100 * 32]; // [t][l] packed accumulators
    __shared__ uint4          s_train[1024];       // per-active-neuron spike bits
    __shared__ unsigned       s_masks[100 * 32];   // [t][chunk] spike bits
    __shared__ unsigned short s_kt[100];           // spikes per timestep
    __shared__ unsigned short s_idx[1024];         // compact -> neuron index
    __shared__ float          s_cval[1024];        // compact -> drive c
    __shared__ unsigned       s_gm[32];
    __shared__ int            s_wbase[32];
    __shared__ int            s_nact;
    __shared__ float          s_feats[5];

    int b   = blockIdx.x;
    int tid = threadIdx.x;
    int wid = tid >> 5;
    int l   = tid & 31;

    if (tid < 5) s_feats[tid] = x[b * 105 + tid];
    __syncthreads();

    // ---- drive c per neuron + compaction (deterministic prefix) ----
    float f0 = s_feats[0], f1 = s_feats[1], f2 = s_feats[2],
          f3 = s_feats[3], f4 = s_feats[4];
    const float* wr = w1 + tid * 5;
    float c = b1[tid] + f0 * wr[0] + f1 * wr[1] + f2 * wr[2] + f3 * wr[3] + f4 * wr[4];
    bool act = c > 0.049995f;   // inclusion margin; excluded neurons provably silent
    unsigned gm = __ballot_sync(0xffffffffu, act);
    if (l == 0) s_gm[wid] = gm;

    // zero accumulators while compaction data settles
    #pragma unroll
    for (int i = tid; i < 3200; i += 1024) s_acc[i] = 0ull;
    __syncthreads();

    if (tid < 32) {
        int cnt = __popc(s_gm[tid]);
        int incl = cnt;
        #pragma unroll
        for (int d = 1; d < 32; d <<= 1) {
            int v = __shfl_up_sync(0xffffffffu, incl, d);
            if (tid >= d) incl += v;
        }
        s_wbase[tid] = incl - cnt;
        if (tid == 31) s_nact = incl;
    }
    __syncthreads();
    if (act) {
        int pos = s_wbase[wid] + __popc(gm & ((1u << l) - 1u));
        s_idx[pos]  = (unsigned short)tid;
        s_cval[pos] = c;
    }
    __syncthreads();

    int nact   = s_nact;
    int chunks = (nact + 31) >> 5;

    // ---- phase 1: LIF dynamics; per-thread trains + per-chunk ballot masks ----
    if (wid < chunks) {
        float cc = (tid < nact) ? s_cval[tid] : -1e30f;
        float mem = 0.f, sp = 0.f;
        unsigned tr[4] = {0u, 0u, 0u, 0u};
        #pragma unroll 4
        for (int t = 0; t < 100; t++) {
            mem = __fmaf_rn(0.95f, mem, cc) - sp;
            bool s = mem > 1.0f;
            unsigned m = __ballot_sync(0xffffffffu, s);
            if (l == 0) s_masks[t * 32 + wid] = m;
            tr[t >> 5] |= ((unsigned)s) << (t & 31);
            sp = s ? 1.0f : 0.0f;
        }
        s_train[tid] = make_uint4(tr[0], tr[1], tr[2], tr[3]);
    }
    __syncthreads();

    // per-timestep spike counts
    if (tid < 100) {
        unsigned k = 0;
        for (int ci = 0; ci < chunks; ci++) k += __popc(s_masks[tid * 32 + ci]);
        s_kt[tid] = (unsigned short)k;
    }

    // ---- phase 2: neuron-major scatter; ONE packed 64-bit atomic per spike ----
    for (int i = wid; i < nact; i += 32) {
        unsigned long long pv = g_w2P[(unsigned)s_idx[i] * 32 + l]; // 256B/warp, once
        uint4 tr = s_train[i];                                      // broadcast LDS.128
        unsigned m;
        m = tr.x;
        while (m) {
            int t = __ffs(m) - 1; m &= m - 1;
            atomicAdd(&s_acc[t * 32 + l], pv);
        }
        m = tr.y;
        while (m) {
            int t = 32 + __ffs(m) - 1; m &= m - 1;
            atomicAdd(&s_acc[t * 32 + l], pv);
        }
        m = tr.z;
        while (m) {
            int t = 64 + __ffs(m) - 1; m &= m - 1;
            atomicAdd(&s_acc[t * 32 + l], pv);
        }
        m = tr.w;
        while (m) {
            int t = 96 + __ffs(m) - 1; m &= m - 1;
            atomicAdd(&s_acc[t * 32 + l], pv);
        }
    }
    __syncthreads();

    // ---- phase 3: decode + layer-2 LIF scan + mean ----
    if (tid < 64) {
        const unsigned* av = (const unsigned*)s_acc;   // [t][o] little-endian view
        float b2o = b2[tid];
        float mem = 0.f, sp = 0.f, sum = 0.f;
        #pragma unroll 4
        for (int t = 0; t < 100; t++) {
            unsigned raw = av[t * 64 + tid];
            int corr = (int)(raw - ((unsigned)s_kt[t] << 21));
            float cur = __fmaf_rn((float)corr, W2_INVSCALE, b2o);
            mem = __fmaf_rn(0.95f, mem, cur) - sp;
            bool s = mem > 1.0f;
            sp = s ? 1.0f : 0.0f;
            sum += sp;
        }
        g_snn[b * 64 + tid] = sum * 0.01f;
    }
}

// ---------------- plain MLP: 8 rows per block --------------------------------
__global__ __launch_bounds__(256) void nn_kernel(const float* __restrict__ x,
                                                 const float* __restrict__ w1,
                                                 const float* __restrict__ b1,
                                                 const float* __restrict__ b2,
                                                 int B) {
    __shared__ float s_h[8 * 1024];   // [r][h]
    __shared__ float s_f[8][5];

    int b0  = blockIdx.x * 8;
    int tid = threadIdx.x;

    if (tid < 40) {
        int r = tid / 5, k = tid % 5;
        s_f[r][k] = x[(b0 + r) * 105 + k];
    }
    __syncthreads();

    for (int j = 0; j < 4; j++) {
        int h = tid + 256 * j;
        const float* wr = w1 + h * 5;
        float w0 = wr[0], w1v = wr[1], w2v = wr[2], w3 = wr[3], w4 = wr[4];
        float bb = b1[h];
        #pragma unroll
        for (int r = 0; r < 8; r++) {
            float v = bb + s_f[r][0] * w0 + s_f[r][1] * w1v + s_f[r][2] * w2v +
                      s_f[r][3] * w3 + s_f[r][4] * w4;
            s_h[r * 1024 + h] = v > 0.f ? v : 0.f;
        }
    }
    __syncthreads();

    int o  = tid & 63;
    int rg = tid >> 6;
    float a0 = 0.f, a1 = 0.f;
    const float* h0 = s_h + (rg * 2) * 1024;
    const float* h1 = s_h + (rg * 2 + 1) * 1024;
    for (int h = 0; h < 1024; h++) {
        float w = g_nnw2T[h * 64 + o];
        a0 += w * h0[h];
        a1 += w * h1[h];
    }
    float bo = b2[o];
    g_nn[(b0 + rg * 2) * 64 + o]     = a0 + bo;
    g_nn[(b0 + rg * 2 + 1) * 64 + o] = a1 + bo;
}

// ---------------- CNN: 16 rows/block, 512 thr (k-split), f32x2 FC ------------
#define CNN_SMEM_BYTES ((25600 + 16 * 102) * 4)

__global__ __launch_bounds__(512, 2) void cnn_kernel(const float* __restrict__ x,
                                                     const float* __restrict__ cw,
                                                     const float* __restrict__ cb,
                                                     const float* __restrict__ fcb,
                                                     int B) {
    extern __shared__ float sm[];
    float* s_p    = sm;            // pooled, transposed: [k=ch*50+j][r] (1600 x 16)
    float* s_wave = sm + 25600;    // [r][102] zero-padded

    __shared__ float s_cw[96];
    __shared__ float s_cb[32];

    int b0  = blockIdx.x * 16;
    int tid = threadIdx.x;

    if (tid < 96) s_cw[tid] = cw[tid];
    if (tid < 32) s_cb[tid] = cb[tid];
    for (int i = tid; i < 16 * 102; i += 512) {
        int r = i / 102, q = i % 102;
        float v = 0.f;
        if (q >= 1 && q <= 100) v = x[(b0 + r) * 105 + 4 + q];
        s_wave[i] = v;
    }
    __syncthreads();

    for (int i = tid; i < 25600; i += 512) {
        int r   = i & 15;
        int pos = i >> 4;
        int ch  = pos / 50;
        int j   = pos - ch * 50;
        const float* wv = s_wave + r * 102 + 2 * j;
        float w0 = s_cw[ch * 3], w1 = s_cw[ch * 3 + 1], w2 = s_cw[ch * 3 + 2];
        float bb = s_cb[ch];
        float c0 = bb + wv[0] * w0 + wv[1] * w1 + wv[2] * w2;
        float c1 = bb + wv[1] * w0 + wv[2] * w1 + wv[3] * w2;
        float m = fmaxf(c0, c1);
        s_p[pos * 16 + r] = m > 0.f ? m : 0.f;
    }
    __syncthreads();

    int o  = tid & 255;
    int kh = tid >> 8;
    unsigned long long a[8];
    #pragma unroll
    for (int q = 0; q < 8; q++) a[q] = 0ull;

    int kbeg = kh * 800;
    const float* fp = g_fcT + (size_t)kbeg * 256 + o;
    const ulonglong2* rp = (const ulonglong2*)s_p + kbeg * 4;

    for (int kk = 0; kk < 800; kk += 4) {
        float w0 = fp[0], w1 = fp[256], w2 = fp[512], w3 = fp[768];
        fp += 1024;
        unsigned long long W[4];
        asm("mov.b64 %0, {%1, %1};" : "=l"(W[0]) : "r"(__float_as_uint(w0)));
        asm("mov.b64 %0, {%1, %1};" : "=l"(W[1]) : "r"(__float_as_uint(w1)));
        asm("mov.b64 %0, {%1, %1};" : "=l"(W[2]) : "r"(__float_as_uint(w2)));
        asm("mov.b64 %0, {%1, %1};" : "=l"(W[3]) : "r"(__float_as_uint(w3)));
        #pragma unroll
        for (int u = 0; u < 4; u++) {
            #pragma unroll
            for (int m2 = 0; m2 < 4; m2++) {
                ulonglong2 v = rp[u * 4 + m2];
                asm("fma.rn.f32x2 %0, %1, %2, %0;" : "+l"(a[2 * m2])     : "l"(v.x), "l"(W[u]));
                asm("fma.rn.f32x2 %0, %1, %2, %0;" : "+l"(a[2 * m2 + 1]) : "l"(v.y), "l"(W[u]));
            }
        }
        rp += 16;
    }

    if (kh == 1) {
        #pragma unroll
        for (int q = 0; q < 8; q++) {
            float lo = __uint_as_float((unsigned)(a[q] & 0xffffffffull));
            float hi = __uint_as_float((unsigned)(a[q] >> 32));
            g_cnn[(b0 + 2 * q) * 256 + o]     = lo;
            g_cnn[(b0 + 2 * q + 1) * 256 + o] = hi;
        }
    }
    __syncthreads();
    if (kh == 0) {
        float fb = fcb[o];
        #pragma unroll
        for (int q = 0; q < 8; q++) {
            float lo = __uint_as_float((unsigned)(a[q] & 0xffffffffull));
            float hi = __uint_as_float((unsigned)(a[q] >> 32));
            int r0 = (b0 + 2 * q) * 256 + o;
            int r1 = (b0 + 2 * q + 1) * 256 + o;
            g_cnn[r0] = lo + fb + g_cnn[r0];
            g_cnn[r1] = hi + fb + g_cnn[r1];
        }
    }
}

// ---------------- combiner ----------------------------------------------------
__global__ __launch_bounds__(256) void comb_kernel(const float* __restrict__ cbias,
                                                   float* __restrict__ out,
                                                   int B) {
    __shared__ float s_c[16 * 384];   // [r][c]
    int b0  = blockIdx.x * 16;
    int tid = threadIdx.x;

    for (int i = tid; i < 16 * 64; i += 256) {
        int r = i >> 6, o = i & 63;
        s_c[r * 384 + o]      = g_snn[(b0 + r) * 64 + o];
        s_c[r * 384 + 64 + o] = g_nn[(b0 + r) * 64 + o];
    }
    for (int i = tid; i < 16 * 256; i += 256) {
        int r = i >> 8, o = i & 255;
        s_c[r * 384 + 128 + o] = g_cnn[(b0 + r) * 256 + o];
    }
    __syncthreads();

    int o  = tid & 63;
    int rg = tid >> 6;
    float a[4] = {0.f, 0.f, 0.f, 0.f};
    for (int c = 0; c < 384; c++) {
        float w = g_combT[c * 64 + o];
        const float* pr = s_c + (rg * 4) * 384 + c;
        a[0] += w * pr[0];
        a[1] += w * pr[384];
        a[2] += w * pr[2 * 384];
        a[3] += w * pr[3 * 384];
    }
    float bo = cbias[o];
    #pragma unroll
    for (int q = 0; q < 4; q++)
        out[(b0 + rg * 4 + q) * 64 + o] = a[q] + bo;
}

// ---------------- launch -------------------------------------------------------
extern "C" void kernel_launch(void* const* d_in, const int* in_sizes, int n_in,
                              void* d_out, int out_size) {
    const float* x      = (const float*)d_in[0];
    const float* snn_w1 = (const float*)d_in[1];
    const float* snn_b1 = (const float*)d_in[2];
    const float* snn_w2 = (const float*)d_in[3];
    const float* snn_b2 = (const float*)d_in[4];
    const float* nn_w1  = (const float*)d_in[5];
    const float* nn_b1  = (const float*)d_in[6];
    const float* nn_w2  = (const float*)d_in[7];
    const float* nn_b2  = (const float*)d_in[8];
    const float* conv_w = (const float*)d_in[9];
    const float* conv_b = (const float*)d_in[10];
    const float* fc_w   = (const float*)d_in[11];
    const float* fc_b   = (const float*)d_in[12];
    const float* comb_w = (const float*)d_in[13];
    const float* comb_b = (const float*)d_in[14];

    int B = in_sizes[0] / 105;

    cudaFuncSetAttribute(cnn_kernel, cudaFuncAttributeMaxDynamicSharedMemorySize,
                         CNN_SMEM_BYTES);

    prep_kernel<<<1600, 256>>>(snn_w2, nn_w2, fc_w, comb_w);
    snn_kernel<<<B, 1024>>>(x, snn_w1, snn_b1, snn_b2, B);
    nn_kernel<<<B / 8, 256>>>(x, nn_w1, nn_b1, nn_b2, B);
    cnn_kernel<<<B / 16, 512, CNN_SMEM_BYTES>>>(x, conv_w, conv_b, fc_b, B);
    comb_kernel<<<B / 16, 256>>>(comb_b, (float*)d_out, B);
}

// round 11
// speedup vs baseline: 1.3105x; 1.3105x over previous
#include <cuda_runtime.h>
#include <cuda_bf16.h>
#include <cstdint>

#define B_MAX 16384

// ---------------- persistent scratch (__device__ globals; no allocations) ----
__device__ float g_w2T[1024 * 64];    // snn_w2 transposed: [h][o] = w2[o][h]
__device__ float g_nnw2T[1024 * 64];  // nn_w2 transposed: [h][o]
__device__ float g_fcT[1600 * 256];   // cnn_fc_w transposed: [k][o]
__device__ float g_combT[384 * 64];   // comb_w transposed: [c][o]
__device__ float g_snn[B_MAX * 64];
__device__ float g_nn[B_MAX * 64];
__device__ float g_cnn[B_MAX * 256];

// ---------------- weight transpose ------------------------------------------
__global__ void prep_kernel(const float* __restrict__ snn_w2,
                            const float* __restrict__ nn_w2,
                            const float* __restrict__ fc_w,
                            const float* __restrict__ comb_w) {
    int i = blockIdx.x * blockDim.x + threadIdx.x;
    if (i < 1024 * 64) {
        int h = i >> 6, o = i & 63;
        g_w2T[i]   = snn_w2[o * 1024 + h];
        g_nnw2T[i] = nn_w2[o * 1024 + h];
    }
    if (i < 1600 * 256) {
        int k = i >> 8, o = i & 255;
        g_fcT[i] = fc_w[o * 1600 + k];
    }
    if (i < 384 * 64) {
        int c = i >> 6, o = i & 63;
        g_combT[i] = comb_w[o * 384 + c];
    }
}

// ---------------- SNN: one block (1024 thr) per batch row --------------------
// Active-neuron compaction (drive c <= ~0.05 provably never spikes). Phase 1:
// chunk-per-warp LIF dynamics write 100-step spike masks. Phase 2: stage active
// w2 rows into SMEM in 128-row tiles (each row loaded from L2 ONCE), then
// warp-per-timestep gathers rows from SMEM with plain fp32 adds — no atomics,
// deterministic ascending-h order, ~3x fewer smem phases than atomic RMW.
__global__ __launch_bounds__(1024, 2) void snn_kernel(const float* __restrict__ x,
                                                      const float* __restrict__ w1,
                                                      const float* __restrict__ b1,
                                                      const float* __restrict__ b2,
                                                      int B) {
    __shared__ float          s_cur2[100 * 64];  // [t][o]  (b2 pre-added)
    __shared__ unsigned       s_masks[100 * 32]; // [t][chunk] spike bits (compact)
    __shared__ float          s_tile[128 * 64];  // staged active rows
    __shared__ unsigned short s_idx[1024];       // compact -> neuron index
    __shared__ float          s_cval[1024];      // compact -> drive c
    __shared__ unsigned       s_gm[32];
    __shared__ int            s_wbase[32];
    __shared__ int            s_nact;
    __shared__ float          s_feats[5];

    int b   = blockIdx.x;
    int tid = threadIdx.x;
    int wid = tid >> 5;
    int l   = tid & 31;

    if (tid < 5) s_feats[tid] = x[b * 105 + tid];
    __syncthreads();

    // ---- drive c per neuron + compaction (deterministic prefix) ----
    float f0 = s_feats[0], f1 = s_feats[1], f2 = s_feats[2],
          f3 = s_feats[3], f4 = s_feats[4];
    const float* wr = w1 + tid * 5;
    float c = b1[tid] + f0 * wr[0] + f1 * wr[1] + f2 * wr[2] + f3 * wr[3] + f4 * wr[4];
    bool act = c > 0.049995f;   // inclusion margin; excluded neurons provably silent
    unsigned gm = __ballot_sync(0xffffffffu, act);
    if (l == 0) s_gm[wid] = gm;
    __syncthreads();
    if (tid < 32) {
        int cnt = __popc(s_gm[tid]);
        int incl = cnt;
        #pragma unroll
        for (int d = 1; d < 32; d <<= 1) {
            int v = __shfl_up_sync(0xffffffffu, incl, d);
            if (tid >= d) incl += v;
        }
        s_wbase[tid] = incl - cnt;
        if (tid == 31) s_nact = incl;
    }
    __syncthreads();
    if (act) {
        int pos = s_wbase[wid] + __popc(gm & ((1u << l) - 1u));
        s_idx[pos]  = (unsigned short)tid;
        s_cval[pos] = c;
    }
    __syncthreads();

    int nact   = s_nact;
    int chunks = (nact + 31) >> 5;      // <= 32

    // ---- phase 1: LIF dynamics, one compact chunk per warp ----
    if (wid < chunks) {
        int i = wid * 32 + l;
        float cc = (i < nact) ? s_cval[i] : -1e30f;
        float mem = 0.f, sp = 0.f;
        #pragma unroll 4
        for (int t = 0; t < 100; t++) {
            mem = __fmaf_rn(0.95f, mem, cc) - sp;
            bool s = mem > 1.0f;
            unsigned m = __ballot_sync(0xffffffffu, s);
            if (l == 0) s_masks[t * 32 + wid] = m;
            sp = s ? 1.0f : 0.0f;
        }
    }
    __syncthreads();

    // ---- phase 2: tiled gather; warp = timestep, lane owns outputs (2l,2l+1) --
    float b20 = b2[2 * l], b21 = b2[2 * l + 1];
    float2 acc[4];
    #pragma unroll
    for (int q = 0; q < 4; q++) acc[q] = make_float2(b20, b21);

    int ntiles = (nact + 127) >> 7;
    for (int T = 0; T < ntiles; T++) {
        int base = T * 128;
        int cnt  = min(128, nact - base);

        // stage: 8 threads per row, 8 floats each (coalesced 2x float4)
        for (int w = tid; w < cnt * 8; w += 1024) {
            int il = w >> 3, c8 = (w & 7) * 8;
            int hh = s_idx[base + il];
            float4 v0 = *(const float4*)(g_w2T + hh * 64 + c8);
            float4 v1 = *(const float4*)(g_w2T + hh * 64 + c8 + 4);
            *(float4*)(s_tile + il * 64 + c8)     = v0;
            *(float4*)(s_tile + il * 64 + c8 + 4) = v1;
        }
        __syncthreads();

        int c0   = base >> 5;              // 4*T
        int cend = min(c0 + 4, chunks);
        #pragma unroll
        for (int q = 0; q < 4; q++) {
            int t = wid + q * 32;
            if (t < 100) {
                float2 a = acc[q];
                for (int ci = c0; ci < cend; ci++) {
                    unsigned m = s_masks[t * 32 + ci];
                    const float* rowb = s_tile + (ci - c0) * 32 * 64;
                    while (m) {
                        int j = __ffs(m) - 1; m &= m - 1;
                        float2 v = *(const float2*)(rowb + j * 64 + 2 * l);
                        a.x += v.x; a.y += v.y;
                    }
                }
                acc[q] = a;
            }
        }
        __syncthreads();   // before next tile overwrites s_tile
    }

    #pragma unroll
    for (int q = 0; q < 4; q++) {
        int t = wid + q * 32;
        if (t < 100) *(float2*)(s_cur2 + t * 64 + 2 * l) = acc[q];
    }
    __syncthreads();

    // ---- phase 3: layer-2 LIF scan + mean ----
    if (tid < 64) {
        float mem = 0.f, sp = 0.f, sum = 0.f;
        #pragma unroll 4
        for (int t = 0; t < 100; t++) {
            mem = __fmaf_rn(0.95f, mem, s_cur2[t * 64 + tid]) - sp;
            bool s = mem > 1.0f;
            sp = s ? 1.0f : 0.0f;
            sum += sp;
        }
        g_snn[b * 64 + tid] = sum * 0.01f;
    }
}

// ---------------- plain MLP: 8 rows per block --------------------------------
__global__ __launch_bounds__(256) void nn_kernel(const float* __restrict__ x,
                                                 const float* __restrict__ w1,
                                                 const float* __restrict__ b1,
                                                 const float* __restrict__ b2,
                                                 int B) {
    __shared__ float s_h[8 * 1024];   // [r][h]
    __shared__ float s_f[8][5];

    int b0  = blockIdx.x * 8;
    int tid = threadIdx.x;

    if (tid < 40) {
        int r = tid / 5, k = tid % 5;
        s_f[r][k] = x[(b0 + r) * 105 + k];
    }
    __syncthreads();

    for (int j = 0; j < 4; j++) {
        int h = tid + 256 * j;
        const float* wr = w1 + h * 5;
        float w0 = wr[0], w1v = wr[1], w2v = wr[2], w3 = wr[3], w4 = wr[4];
        float bb = b1[h];
        #pragma unroll
        for (int r = 0; r < 8; r++) {
            float v = bb + s_f[r][0] * w0 + s_f[r][1] * w1v + s_f[r][2] * w2v +
                      s_f[r][3] * w3 + s_f[r][4] * w4;
            s_h[r * 1024 + h] = v > 0.f ? v : 0.f;
        }
    }
    __syncthreads();

    int o  = tid & 63;
    int rg = tid >> 6;
    float a0 = 0.f, a1 = 0.f;
    const float* h0 = s_h + (rg * 2) * 1024;
    const float* h1 = s_h + (rg * 2 + 1) * 1024;
    for (int h = 0; h < 1024; h++) {
        float w = g_nnw2T[h * 64 + o];
        a0 += w * h0[h];
        a1 += w * h1[h];
    }
    float bo = b2[o];
    g_nn[(b0 + rg * 2) * 64 + o]     = a0 + bo;
    g_nn[(b0 + rg * 2 + 1) * 64 + o] = a1 + bo;
}

// ---------------- CNN: 16 rows/block, 256 thr, 2 outputs/thread, f32x2 FC ----
// W=2: per k each warp does 1 LDG.64 (float2 weights) + 4 LDS.128 broadcast for
// 16 FFMA2 — half the L1 ops per MAC of the W=1 version, making the fma pipe
// the binding resource (floor ~197us).
#define CNN_SMEM_BYTES ((25600 + 16 * 102) * 4)

__global__ __launch_bounds__(256, 2) void cnn_kernel(const float* __restrict__ x,
                                                     const float* __restrict__ cw,
                                                     const float* __restrict__ cb,
                                                     const float* __restrict__ fcb,
                                                     int B) {
    extern __shared__ float sm[];
    float* s_p    = sm;            // pooled, transposed: [k=ch*50+j][r] (1600 x 16)
    float* s_wave = sm + 25600;    // [r][102] zero-padded

    __shared__ float s_cw[96];
    __shared__ float s_cb[32];

    int b0  = blockIdx.x * 16;
    int tid = threadIdx.x;

    if (tid < 96) s_cw[tid] = cw[tid];
    if (tid < 32) s_cb[tid] = cb[tid];
    for (int i = tid; i < 16 * 102; i += 256) {
        int r = i / 102, q = i % 102;
        float v = 0.f;
        if (q >= 1 && q <= 100) v = x[(b0 + r) * 105 + 4 + q];
        s_wave[i] = v;
    }
    __syncthreads();

    // conv(pad=1,k=3) + bias + relu + maxpool2, transposed store
    for (int i = tid; i < 25600; i += 256) {
        int r   = i & 15;
        int pos = i >> 4;
        int ch  = pos / 50;
        int j   = pos - ch * 50;
        const float* wv = s_wave + r * 102 + 2 * j;
        float w0 = s_cw[ch * 3], w1 = s_cw[ch * 3 + 1], w2 = s_cw[ch * 3 + 2];
        float bb = s_cb[ch];
        float c0 = bb + wv[0] * w0 + wv[1] * w1 + wv[2] * w2;
        float c1 = bb + wv[1] * w0 + wv[2] * w1 + wv[3] * w2;
        float m = fmaxf(c0, c1);
        s_p[pos * 16 + r] = m > 0.f ? m : 0.f;
    }
    __syncthreads();

    // FC 1600 -> 256: thread = (o-pair og, k-half kh); outputs 2*og, 2*og+1.
    // 16 f32x2 accumulators: a[oi*8+q] = rows (2q, 2q+1) of output 2*og+oi.
    int og = tid & 127;
    int kh = tid >> 7;
    unsigned long long a[16];
    #pragma unroll
    for (int q = 0; q < 16; q++) a[q] = 0ull;

    int kbeg = kh * 800;
    const float2* fp = (const float2*)g_fcT + (size_t)kbeg * 128 + og;  // [k][og]
    const ulonglong2* rp = (const ulonglong2*)s_p + kbeg * 4;           // 4x16B per k

    for (int kk = 0; kk < 800; kk += 4) {
        float2 w0 = fp[0], w1 = fp[128], w2 = fp[256], w3 = fp[384];
        fp += 512;
        unsigned long long W0[4], W1[4];
        asm("mov.b64 %0, {%1, %1};" : "=l"(W0[0]) : "r"(__float_as_uint(w0.x)));
        asm("mov.b64 %0, {%1, %1};" : "=l"(W1[0]) : "r"(__float_as_uint(w0.y)));
        asm("mov.b64 %0, {%1, %1};" : "=l"(W0[1]) : "r"(__float_as_uint(w1.x)));
        asm("mov.b64 %0, {%1, %1};" : "=l"(W1[1]) : "r"(__float_as_uint(w1.y)));
        asm("mov.b64 %0, {%1, %1};" : "=l"(W0[2]) : "r"(__float_as_uint(w2.x)));
        asm("mov.b64 %0, {%1, %1};" : "=l"(W1[2]) : "r"(__float_as_uint(w2.y)));
        asm("mov.b64 %0, {%1, %1};" : "=l"(W0[3]) : "r"(__float_as_uint(w3.x)));
        asm("mov.b64 %0, {%1, %1};" : "=l"(W1[3]) : "r"(__float_as_uint(w3.y)));
        #pragma unroll
        for (int u = 0; u < 4; u++) {
            #pragma unroll
            for (int m2 = 0; m2 < 4; m2++) {
                ulonglong2 v = rp[u * 4 + m2];
                asm("fma.rn.f32x2 %0, %1, %2, %0;" : "+l"(a[2 * m2])         : "l"(v.x), "l"(W0[u]));
                asm("fma.rn.f32x2 %0, %1, %2, %0;" : "+l"(a[2 * m2 + 1])     : "l"(v.y), "l"(W0[u]));
                asm("fma.rn.f32x2 %0, %1, %2, %0;" : "+l"(a[8 + 2 * m2])     : "l"(v.x), "l"(W1[u]));
                asm("fma.rn.f32x2 %0, %1, %2, %0;" : "+l"(a[8 + 2 * m2 + 1]) : "l"(v.y), "l"(W1[u]));
            }
        }
        rp += 16;
    }

    // combine halves through g_cnn (float2 stores: both outputs of a row)
    int o0 = og * 2;
    if (kh == 1) {
        #pragma unroll
        for (int q = 0; q < 8; q++) {
            float lo0 = __uint_as_float((unsigned)(a[q] & 0xffffffffull));
            float hi0 = __uint_as_float((unsigned)(a[q] >> 32));
            float lo1 = __uint_as_float((unsigned)(a[8 + q] & 0xffffffffull));
            float hi1 = __uint_as_float((unsigned)(a[8 + q] >> 32));
            *(float2*)(g_cnn + (b0 + 2 * q) * 256 + o0)     = make_float2(lo0, lo1);
            *(float2*)(g_cnn + (b0 + 2 * q + 1) * 256 + o0) = make_float2(hi0, hi1);
        }
    }
    __syncthreads();
    if (kh == 0) {
        float fb0 = fcb[o0], fb1 = fcb[o0 + 1];
        #pragma unroll
        for (int q = 0; q < 8; q++) {
            float lo0 = __uint_as_float((unsigned)(a[q] & 0xffffffffull));
            float hi0 = __uint_as_float((unsigned)(a[q] >> 32));
            float lo1 = __uint_as_float((unsigned)(a[8 + q] & 0xffffffffull));
            float hi1 = __uint_as_float((unsigned)(a[8 + q] >> 32));
            float2* p0 = (float2*)(g_cnn + (b0 + 2 * q) * 256 + o0);
            float2* p1 = (float2*)(g_cnn + (b0 + 2 * q + 1) * 256 + o0);
            float2 v0 = *p0, v1 = *p1;
            *p0 = make_float2(lo0 + fb0 + v0.x, lo1 + fb1 + v0.y);
            *p1 = make_float2(hi0 + fb0 + v1.x, hi1 + fb1 + v1.y);
        }
    }
}

// ---------------- combiner ----------------------------------------------------
__global__ __launch_bounds__(256) void comb_kernel(const float* __restrict__ cbias,
                                                   float* __restrict__ out,
                                                   int B) {
    __shared__ float s_c[16 * 384];   // [r][c]
    int b0  = blockIdx.x * 16;
    int tid = threadIdx.x;

    for (int i = tid; i < 16 * 64; i += 256) {
        int r = i >> 6, o = i & 63;
        s_c[r * 384 + o]      = g_snn[(b0 + r) * 64 + o];
        s_c[r * 384 + 64 + o] = g_nn[(b0 + r) * 64 + o];
    }
    for (int i = tid; i < 16 * 256; i += 256) {
        int r = i >> 8, o = i & 255;
        s_c[r * 384 + 128 + o] = g_cnn[(b0 + r) * 256 + o];
    }
    __syncthreads();

    int o  = tid & 63;
    int rg = tid >> 6;
    float a[4] = {0.f, 0.f, 0.f, 0.f};
    for (int c = 0; c < 384; c++) {
        float w = g_combT[c * 64 + o];
        const float* pr = s_c + (rg * 4) * 384 + c;
        a[0] += w * pr[0];
        a[1] += w * pr[384];
        a[2] += w * pr[2 * 384];
        a[3] += w * pr[3 * 384];
    }
    float bo = cbias[o];
    #pragma unroll
    for (int q = 0; q < 4; q++)
        out[(b0 + rg * 4 + q) * 64 + o] = a[q] + bo;
}

// ---------------- launch -------------------------------------------------------
extern "C" void kernel_launch(void* const* d_in, const int* in_sizes, int n_in,
                              void* d_out, int out_size) {
    const float* x      = (const float*)d_in[0];
    const float* snn_w1 = (const float*)d_in[1];
    const float* snn_b1 = (const float*)d_in[2];
    const float* snn_w2 = (const float*)d_in[3];
    const float* snn_b2 = (const float*)d_in[4];
    const float* nn_w1  = (const float*)d_in[5];
    const float* nn_b1  = (const float*)d_in[6];
    const float* nn_w2  = (const float*)d_in[7];
    const float* nn_b2  = (const float*)d_in[8];
    const float* conv_w = (const float*)d_in[9];
    const float* conv_b = (const float*)d_in[10];
    const float* fc_w   = (const float*)d_in[11];
    const float* fc_b   = (const float*)d_in[12];
    const float* comb_w = (const float*)d_in[13];
    const float* comb_b = (const float*)d_in[14];

    int B = in_sizes[0] / 105;

    cudaFuncSetAttribute(cnn_kernel, cudaFuncAttributeMaxDynamicSharedMemorySize,
                         CNN_SMEM_BYTES);

    prep_kernel<<<1600, 256>>>(snn_w2, nn_w2, fc_w, comb_w);
    snn_kernel<<<B, 1024>>>(x, snn_w1, snn_b1, snn_b2, B);
    nn_kernel<<<B / 8, 256>>>(x, nn_w1, nn_b1, nn_b2, B);
    cnn_kernel<<<B / 16, 256, CNN_SMEM_BYTES>>>(x, conv_w, conv_b, fc_b, B);
    comb_kernel<<<B / 16, 256>>>(comb_b, (float*)d_out, B);
}

// round 12
// speedup vs baseline: 1.6779x; 1.2803x over previous
#include <cuda_runtime.h>
#include <cuda_bf16.h>
#include <cstdint>

#define B_MAX 16384

// ---------------- persistent scratch (__device__ globals; no allocations) ----
__device__ int   g_w2I[1024 * 64];    // snn_w2 transposed+paired, fixed-point 2^24:
                                      //   [h][2l]   = w2[l][h]     (output l)
                                      //   [h][2l+1] = w2[l+32][h]  (output l+32)
__device__ float g_nnw2T[1024 * 64];  // nn_w2 transposed: [h][o]
__device__ float g_fcT[1600 * 256];   // cnn_fc_w transposed: [k][o]
__device__ float g_combT[384 * 64];   // comb_w transposed: [c][o]
__device__ float g_snn[B_MAX * 64];
__device__ float g_nn[B_MAX * 64];
__device__ float g_cnn[B_MAX * 256];

#define W2_SCALE    16777216.0f       // 2^24
#define W2_INVSCALE 5.9604645e-8f     // 2^-24

// ---------------- weight transpose / packing ---------------------------------
__global__ void prep_kernel(const float* __restrict__ snn_w2,
                            const float* __restrict__ nn_w2,
                            const float* __restrict__ fc_w,
                            const float* __restrict__ comb_w) {
    int i = blockIdx.x * blockDim.x + threadIdx.x;
    if (i < 1024 * 64) {
        int h = i >> 6, q = i & 63;
        int l = q >> 1;
        int o = (q & 1) ? (l + 32) : l;           // pair (l, l+32) contiguous
        g_w2I[i]   = __float2int_rn(snn_w2[o * 1024 + h] * W2_SCALE);
        g_nnw2T[i] = nn_w2[(i & 63) * 1024 + h];
    }
    if (i < 1600 * 256) {
        int k = i >> 8, o = i & 255;
        g_fcT[i] = fc_w[o * 1600 + k];
    }
    if (i < 384 * 64) {
        int c = i >> 6, o = i & 63;
        g_combT[i] = comb_w[o * 384 + c];
    }
}

// ---------------- SNN: one block (1024 thr) per batch row --------------------
// Active-neuron compaction (drive c <= ~0.05 provably never spikes). Phase 1:
// each active neuron's thread builds its 100-bit spike train in registers.
// Phase 2 (neuron-major): per spike, lane l issues two ATOMS.32 into
// s_acc[t*64+l] and s_acc[t*64+32+l] — stride-4B across lanes, CONFLICT-FREE
// (R8 used (2l,2l+1): stride-8B, 2-way conflict on every atomic). Fixed-point
// 2^24 keeps the sum associative -> deterministic.
__global__ __launch_bounds__(1024, 2) void snn_kernel(const float* __restrict__ x,
                                                      const float* __restrict__ w1,
                                                      const float* __restrict__ b1,
                                                      const float* __restrict__ b2,
                                                      int B) {
    __shared__ int            s_acc[100 * 64];   // [t][o] fixed-point cur2 accum
    __shared__ uint4          s_train[1024];     // per-active-neuron spike bits
    __shared__ unsigned short s_idx[1024];       // compact -> neuron index
    __shared__ float          s_cval[1024];      // compact -> drive c
    __shared__ unsigned       s_gm[32];
    __shared__ int            s_wbase[32];
    __shared__ int            s_nact;
    __shared__ float          s_feats[5];

    int b   = blockIdx.x;
    int tid = threadIdx.x;
    int wid = tid >> 5;
    int l   = tid & 31;

    if (tid < 5) s_feats[tid] = x[b * 105 + tid];
    __syncthreads();

    // ---- drive c per neuron + compaction (deterministic prefix) ----
    float f0 = s_feats[0], f1 = s_feats[1], f2 = s_feats[2],
          f3 = s_feats[3], f4 = s_feats[4];
    const float* wr = w1 + tid * 5;
    float c = b1[tid] + f0 * wr[0] + f1 * wr[1] + f2 * wr[2] + f3 * wr[3] + f4 * wr[4];
    bool act = c > 0.049995f;   // inclusion margin; excluded neurons provably silent
    unsigned gm = __ballot_sync(0xffffffffu, act);
    if (l == 0) s_gm[wid] = gm;

    // zero the cur2 accumulators while compaction data settles
    #pragma unroll
    for (int i = tid; i < 6400; i += 1024) s_acc[i] = 0;
    __syncthreads();

    if (tid < 32) {
        int cnt = __popc(s_gm[tid]);
        int incl = cnt;
        #pragma unroll
        for (int d = 1; d < 32; d <<= 1) {
            int v = __shfl_up_sync(0xffffffffu, incl, d);
            if (tid >= d) incl += v;
        }
        s_wbase[tid] = incl - cnt;
        if (tid == 31) s_nact = incl;
    }
    __syncthreads();
    if (act) {
        int pos = s_wbase[wid] + __popc(gm & ((1u << l) - 1u));
        s_idx[pos]  = (unsigned short)tid;
        s_cval[pos] = c;
    }
    __syncthreads();

    int nact = s_nact;

    // ---- phase 1: LIF dynamics; each active neuron builds its spike train ----
    if (tid < nact) {
        float cc = s_cval[tid];
        float mem = 0.f, sp = 0.f;
        unsigned tr0 = 0, tr1 = 0, tr2 = 0, tr3 = 0;
        #pragma unroll
        for (int u = 0; u < 32; u++) {
            mem = __fmaf_rn(0.95f, mem, cc) - sp;
            bool s = mem > 1.0f; sp = s ? 1.0f : 0.0f;
            tr0 |= ((unsigned)s) << u;
        }
        #pragma unroll
        for (int u = 0; u < 32; u++) {
            mem = __fmaf_rn(0.95f, mem, cc) - sp;
            bool s = mem > 1.0f; sp = s ? 1.0f : 0.0f;
            tr1 |= ((unsigned)s) << u;
        }
        #pragma unroll
        for (int u = 0; u < 32; u++) {
            mem = __fmaf_rn(0.95f, mem, cc) - sp;
            bool s = mem > 1.0f; sp = s ? 1.0f : 0.0f;
            tr2 |= ((unsigned)s) << u;
        }
        #pragma unroll
        for (int u = 0; u < 4; u++) {
            mem = __fmaf_rn(0.95f, mem, cc) - sp;
            bool s = mem > 1.0f; sp = s ? 1.0f : 0.0f;
            tr3 |= ((unsigned)s) << u;
        }
        s_train[tid] = make_uint4(tr0, tr1, tr2, tr3);
    }
    __syncthreads();

    // ---- phase 2: neuron-major scatter, conflict-free atomic addressing ----
    const int2* w2p = (const int2*)g_w2I;   // [h][32] int2 = (out l, out l+32)
    for (int i = wid; i < nact; i += 32) {
        int2 v  = w2p[(unsigned)s_idx[i] * 32 + l];   // one 256B row load per neuron
        uint4 tr = s_train[i];                        // broadcast LDS.128
        unsigned m;
        m = tr.x;
        while (m) {
            int t = __ffs(m) - 1; m &= m - 1;
            atomicAdd(&s_acc[t * 64 + l],      v.x);
            atomicAdd(&s_acc[t * 64 + 32 + l], v.y);
        }
        m = tr.y;
        while (m) {
            int t = 32 + __ffs(m) - 1; m &= m - 1;
            atomicAdd(&s_acc[t * 64 + l],      v.x);
            atomicAdd(&s_acc[t * 64 + 32 + l], v.y);
        }
        m = tr.z;
        while (m) {
            int t = 64 + __ffs(m) - 1; m &= m - 1;
            atomicAdd(&s_acc[t * 64 + l],      v.x);
            atomicAdd(&s_acc[t * 64 + 32 + l], v.y);
        }
        m = tr.w;
        while (m) {
            int t = 96 + __ffs(m) - 1; m &= m - 1;
            atomicAdd(&s_acc[t * 64 + l],      v.x);
            atomicAdd(&s_acc[t * 64 + 32 + l], v.y);
        }
    }
    __syncthreads();

    // ---- phase 3: layer-2 LIF scan + mean ----
    if (tid < 64) {
        float b2o = b2[tid];
        float mem = 0.f, sp = 0.f, sum = 0.f;
        #pragma unroll 4
        for (int t = 0; t < 100; t++) {
            float cur = __fmaf_rn((float)s_acc[t * 64 + tid], W2_INVSCALE, b2o);
            mem = __fmaf_rn(0.95f, mem, cur) - sp;
            bool s = mem > 1.0f;
            sp = s ? 1.0f : 0.0f;
            sum += sp;
        }
        g_snn[b * 64 + tid] = sum * 0.01f;
    }
}

// ---------------- plain MLP: 8 rows per block --------------------------------
__global__ __launch_bounds__(256) void nn_kernel(const float* __restrict__ x,
                                                 const float* __restrict__ w1,
                                                 const float* __restrict__ b1,
                                                 const float* __restrict__ b2,
                                                 int B) {
    __shared__ float s_h[8 * 1024];   // [r][h]
    __shared__ float s_f[8][5];

    int b0  = blockIdx.x * 8;
    int tid = threadIdx.x;

    if (tid < 40) {
        int r = tid / 5, k = tid % 5;
        s_f[r][k] = x[(b0 + r) * 105 + k];
    }
    __syncthreads();

    for (int j = 0; j < 4; j++) {
        int h = tid + 256 * j;
        const float* wr = w1 + h * 5;
        float w0 = wr[0], w1v = wr[1], w2v = wr[2], w3 = wr[3], w4 = wr[4];
        float bb = b1[h];
        #pragma unroll
        for (int r = 0; r < 8; r++) {
            float v = bb + s_f[r][0] * w0 + s_f[r][1] * w1v + s_f[r][2] * w2v +
                      s_f[r][3] * w3 + s_f[r][4] * w4;
            s_h[r * 1024 + h] = v > 0.f ? v : 0.f;
        }
    }
    __syncthreads();

    int o  = tid & 63;
    int rg = tid >> 6;
    float a0 = 0.f, a1 = 0.f;
    const float* h0 = s_h + (rg * 2) * 1024;
    const float* h1 = s_h + (rg * 2 + 1) * 1024;
    for (int h = 0; h < 1024; h++) {
        float w = g_nnw2T[h * 64 + o];
        a0 += w * h0[h];
        a1 += w * h1[h];
    }
    float bo = b2[o];
    g_nn[(b0 + rg * 2) * 64 + o]     = a0 + bo;
    g_nn[(b0 + rg * 2 + 1) * 64 + o] = a1 + bo;
}

// ---------------- CNN: 16 rows/block, 256 thr, 2 outputs/thread, f32x2 FC ----
// (unchanged from R11: measured 292us, fma 60%)
#define CNN_SMEM_BYTES ((25600 + 16 * 102) * 4)

__global__ __launch_bounds__(256, 2) void cnn_kernel(const float* __restrict__ x,
                                                     const float* __restrict__ cw,
                                                     const float* __restrict__ cb,
                                                     const float* __restrict__ fcb,
                                                     int B) {
    extern __shared__ float sm[];
    float* s_p    = sm;            // pooled, transposed: [k=ch*50+j][r] (1600 x 16)
    float* s_wave = sm + 25600;    // [r][102] zero-padded

    __shared__ float s_cw[96];
    __shared__ float s_cb[32];

    int b0  = blockIdx.x * 16;
    int tid = threadIdx.x;

    if (tid < 96) s_cw[tid] = cw[tid];
    if (tid < 32) s_cb[tid] = cb[tid];
    for (int i = tid; i < 16 * 102; i += 256) {
        int r = i / 102, q = i % 102;
        float v = 0.f;
        if (q >= 1 && q <= 100) v = x[(b0 + r) * 105 + 4 + q];
        s_wave[i] = v;
    }
    __syncthreads();

    for (int i = tid; i < 25600; i += 256) {
        int r   = i & 15;
        int pos = i >> 4;
        int ch  = pos / 50;
        int j   = pos - ch * 50;
        const float* wv = s_wave + r * 102 + 2 * j;
        float w0 = s_cw[ch * 3], w1 = s_cw[ch * 3 + 1], w2 = s_cw[ch * 3 + 2];
        float bb = s_cb[ch];
        float c0 = bb + wv[0] * w0 + wv[1] * w1 + wv[2] * w2;
        float c1 = bb + wv[1] * w0 + wv[2] * w1 + wv[3] * w2;
        float m = fmaxf(c0, c1);
        s_p[pos * 16 + r] = m > 0.f ? m : 0.f;
    }
    __syncthreads();

    int og = tid & 127;
    int kh = tid >> 7;
    unsigned long long a[16];
    #pragma unroll
    for (int q = 0; q < 16; q++) a[q] = 0ull;

    int kbeg = kh * 800;
    const float2* fp = (const float2*)g_fcT + (size_t)kbeg * 128 + og;
    const ulonglong2* rp = (const ulonglong2*)s_p + kbeg * 4;

    for (int kk = 0; kk < 800; kk += 4) {
        float2 w0 = fp[0], w1 = fp[128], w2 = fp[256], w3 = fp[384];
        fp += 512;
        unsigned long long W0[4], W1[4];
        asm("mov.b64 %0, {%1, %1};" : "=l"(W0[0]) : "r"(__float_as_uint(w0.x)));
        asm("mov.b64 %0, {%1, %1};" : "=l"(W1[0]) : "r"(__float_as_uint(w0.y)));
        asm("mov.b64 %0, {%1, %1};" : "=l"(W0[1]) : "r"(__float_as_uint(w1.x)));
        asm("mov.b64 %0, {%1, %1};" : "=l"(W1[1]) : "r"(__float_as_uint(w1.y)));
        asm("mov.b64 %0, {%1, %1};" : "=l"(W0[2]) : "r"(__float_as_uint(w2.x)));
        asm("mov.b64 %0, {%1, %1};" : "=l"(W1[2]) : "r"(__float_as_uint(w2.y)));
        asm("mov.b64 %0, {%1, %1};" : "=l"(W0[3]) : "r"(__float_as_uint(w3.x)));
        asm("mov.b64 %0, {%1, %1};" : "=l"(W1[3]) : "r"(__float_as_uint(w3.y)));
        #pragma unroll
        for (int u = 0; u < 4; u++) {
            #pragma unroll
            for (int m2 = 0; m2 < 4; m2++) {
                ulonglong2 v = rp[u * 4 + m2];
                asm("fma.rn.f32x2 %0, %1, %2, %0;" : "+l"(a[2 * m2])         : "l"(v.x), "l"(W0[u]));
                asm("fma.rn.f32x2 %0, %1, %2, %0;" : "+l"(a[2 * m2 + 1])     : "l"(v.y), "l"(W0[u]));
                asm("fma.rn.f32x2 %0, %1, %2, %0;" : "+l"(a[8 + 2 * m2])     : "l"(v.x), "l"(W1[u]));
                asm("fma.rn.f32x2 %0, %1, %2, %0;" : "+l"(a[8 + 2 * m2 + 1]) : "l"(v.y), "l"(W1[u]));
            }
        }
        rp += 16;
    }

    int o0 = og * 2;
    if (kh == 1) {
        #pragma unroll
        for (int q = 0; q < 8; q++) {
            float lo0 = __uint_as_float((unsigned)(a[q] & 0xffffffffull));
            float hi0 = __uint_as_float((unsigned)(a[q] >> 32));
            float lo1 = __uint_as_float((unsigned)(a[8 + q] & 0xffffffffull));
            float hi1 = __uint_as_float((unsigned)(a[8 + q] >> 32));
            *(float2*)(g_cnn + (b0 + 2 * q) * 256 + o0)     = make_float2(lo0, lo1);
            *(float2*)(g_cnn + (b0 + 2 * q + 1) * 256 + o0) = make_float2(hi0, hi1);
        }
    }
    __syncthreads();
    if (kh == 0) {
        float fb0 = fcb[o0], fb1 = fcb[o0 + 1];
        #pragma unroll
        for (int q = 0; q < 8; q++) {
            float lo0 = __uint_as_float((unsigned)(a[q] & 0xffffffffull));
            float hi0 = __uint_as_float((unsigned)(a[q] >> 32));
            float lo1 = __uint_as_float((unsigned)(a[8 + q] & 0xffffffffull));
            float hi1 = __uint_as_float((unsigned)(a[8 + q] >> 32));
            float2* p0 = (float2*)(g_cnn + (b0 + 2 * q) * 256 + o0);
            float2* p1 = (float2*)(g_cnn + (b0 + 2 * q + 1) * 256 + o0);
            float2 v0 = *p0, v1 = *p1;
            *p0 = make_float2(lo0 + fb0 + v0.x, lo1 + fb1 + v0.y);
            *p1 = make_float2(hi0 + fb0 + v1.x, hi1 + fb1 + v1.y);
        }
    }
}

// ---------------- combiner ----------------------------------------------------
__global__ __launch_bounds__(256) void comb_kernel(const float* __restrict__ cbias,
                                                   float* __restrict__ out,
                                                   int B) {
    __shared__ float s_c[16 * 384];   // [r][c]
    int b0  = blockIdx.x * 16;
    int tid = threadIdx.x;

    for (int i = tid; i < 16 * 64; i += 256) {
        int r = i >> 6, o = i & 63;
        s_c[r * 384 + o]      = g_snn[(b0 + r) * 64 + o];
        s_c[r * 384 + 64 + o] = g_nn[(b0 + r) * 64 + o];
    }
    for (int i = tid; i < 16 * 256; i += 256) {
        int r = i >> 8, o = i & 255;
        s_c[r * 384 + 128 + o] = g_cnn[(b0 + r) * 256 + o];
    }
    __syncthreads();

    int o  = tid & 63;
    int rg = tid >> 6;
    float a[4] = {0.f, 0.f, 0.f, 0.f};
    for (int c = 0; c < 384; c++) {
        float w = g_combT[c * 64 + o];
        const float* pr = s_c + (rg * 4) * 384 + c;
        a[0] += w * pr[0];
        a[1] += w * pr[384];
        a[2] += w * pr[2 * 384];
        a[3] += w * pr[3 * 384];
    }
    float bo = cbias[o];
    #pragma unroll
    for (int q = 0; q < 4; q++)
        out[(b0 + rg * 4 + q) * 64 + o] = a[q] + bo;
}

// ---------------- launch -------------------------------------------------------
extern "C" void kernel_launch(void* const* d_in, const int* in_sizes, int n_in,
                              void* d_out, int out_size) {
    const float* x      = (const float*)d_in[0];
    const float* snn_w1 = (const float*)d_in[1];
    const float* snn_b1 = (const float*)d_in[2];
    const float* snn_w2 = (const float*)d_in[3];
    const float* snn_b2 = (const float*)d_in[4];
    const float* nn_w1  = (const float*)d_in[5];
    const float* nn_b1  = (const float*)d_in[6];
    const float* nn_w2  = (const float*)d_in[7];
    const float* nn_b2  = (const float*)d_in[8];
    const float* conv_w = (const float*)d_in[9];
    const float* conv_b = (const float*)d_in[10];
    const float* fc_w   = (const float*)d_in[11];
    const float* fc_b   = (const float*)d_in[12];
    const float* comb_w = (const float*)d_in[13];
    const float* comb_b = (const float*)d_in[14];

    int B = in_sizes[0] / 105;

    cudaFuncSetAttribute(cnn_kernel, cudaFuncAttributeMaxDynamicSharedMemorySize,
                         CNN_SMEM_BYTES);

    prep_kernel<<<1600, 256>>>(snn_w2, nn_w2, fc_w, comb_w);
    snn_kernel<<<B, 1024>>>(x, snn_w1, snn_b1, snn_b2, B);
    nn_kernel<<<B / 8, 256>>>(x, nn_w1, nn_b1, nn_b2, B);
    cnn_kernel<<<B / 16, 256, CNN_SMEM_BYTES>>>(x, conv_w, conv_b, fc_b, B);
    comb_kernel<<<B / 16, 256>>>(comb_b, (float*)d_out, B);
}

// round 13
// speedup vs baseline: 1.6922x; 1.0085x over previous
#include <cuda_runtime.h>
#include <cuda_bf16.h>
#include <cstdint>

#define B_MAX 16384

// ---------------- persistent scratch (__device__ globals; no allocations) ----
__device__ int   g_w2I[1024 * 64];    // snn_w2 transposed+paired, fixed-point 2^24:
                                      //   [h][2l]   = w2[l][h]     (output l)
                                      //   [h][2l+1] = w2[l+32][h]  (output l+32)
__device__ float g_nnw2T[1024 * 64];  // nn_w2 transposed: [h][o]
__device__ float g_fcT[1600 * 256];   // cnn_fc_w transposed: [k][o]
__device__ float g_combT[384 * 64];   // comb_w transposed: [c][o]
__device__ float g_snn[B_MAX * 64];
__device__ float g_nn[B_MAX * 64];
__device__ float g_cnn[B_MAX * 256];

#define W2_SCALE    16777216.0f       // 2^24
#define W2_INVSCALE 5.9604645e-8f     // 2^-24

// ---------------- weight transpose / packing ---------------------------------
__global__ void prep_kernel(const float* __restrict__ snn_w2,
                            const float* __restrict__ nn_w2,
                            const float* __restrict__ fc_w,
                            const float* __restrict__ comb_w) {
    int i = blockIdx.x * blockDim.x + threadIdx.x;
    if (i < 1024 * 64) {
        int h = i >> 6, q = i & 63;
        int l = q >> 1;
        int o = (q & 1) ? (l + 32) : l;           // pair (l, l+32) contiguous
        g_w2I[i]   = __float2int_rn(snn_w2[o * 1024 + h] * W2_SCALE);
        g_nnw2T[i] = nn_w2[(i & 63) * 1024 + h];
    }
    if (i < 1600 * 256) {
        int k = i >> 8, o = i & 255;
        g_fcT[i] = fc_w[o * 1600 + k];
    }
    if (i < 384 * 64) {
        int c = i >> 6, o = i & 63;
        g_combT[i] = comb_w[o * 384 + c];
    }
}

// ---------------- SNN: one block (1024 thr) per batch row --------------------
// (unchanged from R12: measured ~830us; conflict-free ATOMS.32 scatter,
// fixed-point 2^24 -> deterministic, rel_err 5.4e-7)
__global__ __launch_bounds__(1024, 2) void snn_kernel(const float* __restrict__ x,
                                                      const float* __restrict__ w1,
                                                      const float* __restrict__ b1,
                                                      const float* __restrict__ b2,
                                                      int B) {
    __shared__ int            s_acc[100 * 64];   // [t][o] fixed-point cur2 accum
    __shared__ uint4          s_train[1024];     // per-active-neuron spike bits
    __shared__ unsigned short s_idx[1024];       // compact -> neuron index
    __shared__ float          s_cval[1024];      // compact -> drive c
    __shared__ unsigned       s_gm[32];
    __shared__ int            s_wbase[32];
    __shared__ int            s_nact;
    __shared__ float          s_feats[5];

    int b   = blockIdx.x;
    int tid = threadIdx.x;
    int wid = tid >> 5;
    int l   = tid & 31;

    if (tid < 5) s_feats[tid] = x[b * 105 + tid];
    __syncthreads();

    // ---- drive c per neuron + compaction (deterministic prefix) ----
    float f0 = s_feats[0], f1 = s_feats[1], f2 = s_feats[2],
          f3 = s_feats[3], f4 = s_feats[4];
    const float* wr = w1 + tid * 5;
    float c = b1[tid] + f0 * wr[0] + f1 * wr[1] + f2 * wr[2] + f3 * wr[3] + f4 * wr[4];
    bool act = c > 0.049995f;   // inclusion margin; excluded neurons provably silent
    unsigned gm = __ballot_sync(0xffffffffu, act);
    if (l == 0) s_gm[wid] = gm;

    // zero the cur2 accumulators while compaction data settles
    #pragma unroll
    for (int i = tid; i < 6400; i += 1024) s_acc[i] = 0;
    __syncthreads();

    if (tid < 32) {
        int cnt = __popc(s_gm[tid]);
        int incl = cnt;
        #pragma unroll
        for (int d = 1; d < 32; d <<= 1) {
            int v = __shfl_up_sync(0xffffffffu, incl, d);
            if (tid >= d) incl += v;
        }
        s_wbase[tid] = incl - cnt;
        if (tid == 31) s_nact = incl;
    }
    __syncthreads();
    if (act) {
        int pos = s_wbase[wid] + __popc(gm & ((1u << l) - 1u));
        s_idx[pos]  = (unsigned short)tid;
        s_cval[pos] = c;
    }
    __syncthreads();

    int nact = s_nact;

    // ---- phase 1: LIF dynamics; each active neuron builds its spike train ----
    if (tid < nact) {
        float cc = s_cval[tid];
        float mem = 0.f, sp = 0.f;
        unsigned tr0 = 0, tr1 = 0, tr2 = 0, tr3 = 0;
        #pragma unroll
        for (int u = 0; u < 32; u++) {
            mem = __fmaf_rn(0.95f, mem, cc) - sp;
            bool s = mem > 1.0f; sp = s ? 1.0f : 0.0f;
            tr0 |= ((unsigned)s) << u;
        }
        #pragma unroll
        for (int u = 0; u < 32; u++) {
            mem = __fmaf_rn(0.95f, mem, cc) - sp;
            bool s = mem > 1.0f; sp = s ? 1.0f : 0.0f;
            tr1 |= ((unsigned)s) << u;
        }
        #pragma unroll
        for (int u = 0; u < 32; u++) {
            mem = __fmaf_rn(0.95f, mem, cc) - sp;
            bool s = mem > 1.0f; sp = s ? 1.0f : 0.0f;
            tr2 |= ((unsigned)s) << u;
        }
        #pragma unroll
        for (int u = 0; u < 4; u++) {
            mem = __fmaf_rn(0.95f, mem, cc) - sp;
            bool s = mem > 1.0f; sp = s ? 1.0f : 0.0f;
            tr3 |= ((unsigned)s) << u;
        }
        s_train[tid] = make_uint4(tr0, tr1, tr2, tr3);
    }
    __syncthreads();

    // ---- phase 2: neuron-major scatter, conflict-free atomic addressing ----
    const int2* w2p = (const int2*)g_w2I;   // [h][32] int2 = (out l, out l+32)
    for (int i = wid; i < nact; i += 32) {
        int2 v  = w2p[(unsigned)s_idx[i] * 32 + l];   // one 256B row load per neuron
        uint4 tr = s_train[i];                        // broadcast LDS.128
        unsigned m;
        m = tr.x;
        while (m) {
            int t = __ffs(m) - 1; m &= m - 1;
            atomicAdd(&s_acc[t * 64 + l],      v.x);
            atomicAdd(&s_acc[t * 64 + 32 + l], v.y);
        }
        m = tr.y;
        while (m) {
            int t = 32 + __ffs(m) - 1; m &= m - 1;
            atomicAdd(&s_acc[t * 64 + l],      v.x);
            atomicAdd(&s_acc[t * 64 + 32 + l], v.y);
        }
        m = tr.z;
        while (m) {
            int t = 64 + __ffs(m) - 1; m &= m - 1;
            atomicAdd(&s_acc[t * 64 + l],      v.x);
            atomicAdd(&s_acc[t * 64 + 32 + l], v.y);
        }
        m = tr.w;
        while (m) {
            int t = 96 + __ffs(m) - 1; m &= m - 1;
            atomicAdd(&s_acc[t * 64 + l],      v.x);
            atomicAdd(&s_acc[t * 64 + 32 + l], v.y);
        }
    }
    __syncthreads();

    // ---- phase 3: layer-2 LIF scan + mean ----
    if (tid < 64) {
        float b2o = b2[tid];
        float mem = 0.f, sp = 0.f, sum = 0.f;
        #pragma unroll 4
        for (int t = 0; t < 100; t++) {
            float cur = __fmaf_rn((float)s_acc[t * 64 + tid], W2_INVSCALE, b2o);
            mem = __fmaf_rn(0.95f, mem, cur) - sp;
            bool s = mem > 1.0f;
            sp = s ? 1.0f : 0.0f;
            sum += sp;
        }
        g_snn[b * 64 + tid] = sum * 0.01f;
    }
}

// ---------------- plain MLP: 8 rows per block --------------------------------
__global__ __launch_bounds__(256) void nn_kernel(const float* __restrict__ x,
                                                 const float* __restrict__ w1,
                                                 const float* __restrict__ b1,
                                                 const float* __restrict__ b2,
                                                 int B) {
    __shared__ float s_h[8 * 1024];   // [r][h]
    __shared__ float s_f[8][5];

    int b0  = blockIdx.x * 8;
    int tid = threadIdx.x;

    if (tid < 40) {
        int r = tid / 5, k = tid % 5;
        s_f[r][k] = x[(b0 + r) * 105 + k];
    }
    __syncthreads();

    for (int j = 0; j < 4; j++) {
        int h = tid + 256 * j;
        const float* wr = w1 + h * 5;
        float w0 = wr[0], w1v = wr[1], w2v = wr[2], w3 = wr[3], w4 = wr[4];
        float bb = b1[h];
        #pragma unroll
        for (int r = 0; r < 8; r++) {
            float v = bb + s_f[r][0] * w0 + s_f[r][1] * w1v + s_f[r][2] * w2v +
                      s_f[r][3] * w3 + s_f[r][4] * w4;
            s_h[r * 1024 + h] = v > 0.f ? v : 0.f;
        }
    }
    __syncthreads();

    int o  = tid & 63;
    int rg = tid >> 6;
    float a0 = 0.f, a1 = 0.f;
    const float* h0 = s_h + (rg * 2) * 1024;
    const float* h1 = s_h + (rg * 2 + 1) * 1024;
    for (int h = 0; h < 1024; h++) {
        float w = g_nnw2T[h * 64 + o];
        a0 += w * h0[h];
        a1 += w * h1[h];
    }
    float bo = b2[o];
    g_nn[(b0 + rg * 2) * 64 + o]     = a0 + bo;
    g_nn[(b0 + rg * 2 + 1) * 64 + o] = a1 + bo;
}

// ---------------- CNN: 16 rows/block, 256 thr, 2 outputs/thread, f32x2 FC ----
// (unchanged from R12: measured 289us, fma 60%)
#define CNN_SMEM_BYTES ((25600 + 16 * 102) * 4)

__global__ __launch_bounds__(256, 2) void cnn_kernel(const float* __restrict__ x,
                                                     const float* __restrict__ cw,
                                                     const float* __restrict__ cb,
                                                     const float* __restrict__ fcb,
                                                     int B) {
    extern __shared__ float sm[];
    float* s_p    = sm;            // pooled, transposed: [k=ch*50+j][r] (1600 x 16)
    float* s_wave = sm + 25600;    // [r][102] zero-padded

    __shared__ float s_cw[96];
    __shared__ float s_cb[32];

    int b0  = blockIdx.x * 16;
    int tid = threadIdx.x;

    if (tid < 96) s_cw[tid] = cw[tid];
    if (tid < 32) s_cb[tid] = cb[tid];
    for (int i = tid; i < 16 * 102; i += 256) {
        int r = i / 102, q = i % 102;
        float v = 0.f;
        if (q >= 1 && q <= 100) v = x[(b0 + r) * 105 + 4 + q];
        s_wave[i] = v;
    }
    __syncthreads();

    for (int i = tid; i < 25600; i += 256) {
        int r   = i & 15;
        int pos = i >> 4;
        int ch  = pos / 50;
        int j   = pos - ch * 50;
        const float* wv = s_wave + r * 102 + 2 * j;
        float w0 = s_cw[ch * 3], w1 = s_cw[ch * 3 + 1], w2 = s_cw[ch * 3 + 2];
        float bb = s_cb[ch];
        float c0 = bb + wv[0] * w0 + wv[1] * w1 + wv[2] * w2;
        float c1 = bb + wv[1] * w0 + wv[2] * w1 + wv[3] * w2;
        float m = fmaxf(c0, c1);
        s_p[pos * 16 + r] = m > 0.f ? m : 0.f;
    }
    __syncthreads();

    int og = tid & 127;
    int kh = tid >> 7;
    unsigned long long a[16];
    #pragma unroll
    for (int q = 0; q < 16; q++) a[q] = 0ull;

    int kbeg = kh * 800;
    const float2* fp = (const float2*)g_fcT + (size_t)kbeg * 128 + og;
    const ulonglong2* rp = (const ulonglong2*)s_p + kbeg * 4;

    for (int kk = 0; kk < 800; kk += 4) {
        float2 w0 = fp[0], w1 = fp[128], w2 = fp[256], w3 = fp[384];
        fp += 512;
        unsigned long long W0[4], W1[4];
        asm("mov.b64 %0, {%1, %1};" : "=l"(W0[0]) : "r"(__float_as_uint(w0.x)));
        asm("mov.b64 %0, {%1, %1};" : "=l"(W1[0]) : "r"(__float_as_uint(w0.y)));
        asm("mov.b64 %0, {%1, %1};" : "=l"(W0[1]) : "r"(__float_as_uint(w1.x)));
        asm("mov.b64 %0, {%1, %1};" : "=l"(W1[1]) : "r"(__float_as_uint(w1.y)));
        asm("mov.b64 %0, {%1, %1};" : "=l"(W0[2]) : "r"(__float_as_uint(w2.x)));
        asm("mov.b64 %0, {%1, %1};" : "=l"(W1[2]) : "r"(__float_as_uint(w2.y)));
        asm("mov.b64 %0, {%1, %1};" : "=l"(W0[3]) : "r"(__float_as_uint(w3.x)));
        asm("mov.b64 %0, {%1, %1};" : "=l"(W1[3]) : "r"(__float_as_uint(w3.y)));
        #pragma unroll
        for (int u = 0; u < 4; u++) {
            #pragma unroll
            for (int m2 = 0; m2 < 4; m2++) {
                ulonglong2 v = rp[u * 4 + m2];
                asm("fma.rn.f32x2 %0, %1, %2, %0;" : "+l"(a[2 * m2])         : "l"(v.x), "l"(W0[u]));
                asm("fma.rn.f32x2 %0, %1, %2, %0;" : "+l"(a[2 * m2 + 1])     : "l"(v.y), "l"(W0[u]));
                asm("fma.rn.f32x2 %0, %1, %2, %0;" : "+l"(a[8 + 2 * m2])     : "l"(v.x), "l"(W1[u]));
                asm("fma.rn.f32x2 %0, %1, %2, %0;" : "+l"(a[8 + 2 * m2 + 1]) : "l"(v.y), "l"(W1[u]));
            }
        }
        rp += 16;
    }

    int o0 = og * 2;
    if (kh == 1) {
        #pragma unroll
        for (int q = 0; q < 8; q++) {
            float lo0 = __uint_as_float((unsigned)(a[q] & 0xffffffffull));
            float hi0 = __uint_as_float((unsigned)(a[q] >> 32));
            float lo1 = __uint_as_float((unsigned)(a[8 + q] & 0xffffffffull));
            float hi1 = __uint_as_float((unsigned)(a[8 + q] >> 32));
            *(float2*)(g_cnn + (b0 + 2 * q) * 256 + o0)     = make_float2(lo0, lo1);
            *(float2*)(g_cnn + (b0 + 2 * q + 1) * 256 + o0) = make_float2(hi0, hi1);
        }
    }
    __syncthreads();
    if (kh == 0) {
        float fb0 = fcb[o0], fb1 = fcb[o0 + 1];
        #pragma unroll
        for (int q = 0; q < 8; q++) {
            float lo0 = __uint_as_float((unsigned)(a[q] & 0xffffffffull));
            float hi0 = __uint_as_float((unsigned)(a[q] >> 32));
            float lo1 = __uint_as_float((unsigned)(a[8 + q] & 0xffffffffull));
            float hi1 = __uint_as_float((unsigned)(a[8 + q] >> 32));
            float2* p0 = (float2*)(g_cnn + (b0 + 2 * q) * 256 + o0);
            float2* p1 = (float2*)(g_cnn + (b0 + 2 * q + 1) * 256 + o0);
            float2 v0 = *p0, v1 = *p1;
            *p0 = make_float2(lo0 + fb0 + v0.x, lo1 + fb1 + v0.y);
            *p1 = make_float2(hi0 + fb0 + v1.x, hi1 + fb1 + v1.y);
        }
    }
}

// ---------------- combiner ----------------------------------------------------
__global__ __launch_bounds__(256) void comb_kernel(const float* __restrict__ cbias,
                                                   float* __restrict__ out,
                                                   int B) {
    __shared__ float s_c[16 * 384];   // [r][c]
    int b0  = blockIdx.x * 16;
    int tid = threadIdx.x;

    for (int i = tid; i < 16 * 64; i += 256) {
        int r = i >> 6, o = i & 63;
        s_c[r * 384 + o]      = g_snn[(b0 + r) * 64 + o];
        s_c[r * 384 + 64 + o] = g_nn[(b0 + r) * 64 + o];
    }
    for (int i = tid; i < 16 * 256; i += 256) {
        int r = i >> 8, o = i & 255;
        s_c[r * 384 + 128 + o] = g_cnn[(b0 + r) * 256 + o];
    }
    __syncthreads();

    int o  = tid & 63;
    int rg = tid >> 6;
    float a[4] = {0.f, 0.f, 0.f, 0.f};
    for (int c = 0; c < 384; c++) {
        float w = g_combT[c * 64 + o];
        const float* pr = s_c + (rg * 4) * 384 + c;
        a[0] += w * pr[0];
        a[1] += w * pr[384];
        a[2] += w * pr[2 * 384];
        a[3] += w * pr[3 * 384];
    }
    float bo = cbias[o];
    #pragma unroll
    for (int q = 0; q < 4; q++)
        out[(b0 + rg * 4 + q) * 64 + o] = a[q] + bo;
}

// ---------------- launch -------------------------------------------------------
// Single change vs R12: fork cnn (s1) and nn (s2) onto side streams so they run
// under the snn shadow (snn: smem-atomic bound; cnn: fma bound; nn: LDG-latency
// bound — disjoint resources). comb joins all branches. Event-fork capture
// pattern proven graph-safe in R9.
extern "C" void kernel_launch(void* const* d_in, const int* in_sizes, int n_in,
                              void* d_out, int out_size) {
    const float* x      = (const float*)d_in[0];
    const float* snn_w1 = (const float*)d_in[1];
    const float* snn_b1 = (const float*)d_in[2];
    const float* snn_w2 = (const float*)d_in[3];
    const float* snn_b2 = (const float*)d_in[4];
    const float* nn_w1  = (const float*)d_in[5];
    const float* nn_b1  = (const float*)d_in[6];
    const float* nn_w2  = (const float*)d_in[7];
    const float* nn_b2  = (const float*)d_in[8];
    const float* conv_w = (const float*)d_in[9];
    const float* conv_b = (const float*)d_in[10];
    const float* fc_w   = (const float*)d_in[11];
    const float* fc_b   = (const float*)d_in[12];
    const float* comb_w = (const float*)d_in[13];
    const float* comb_b = (const float*)d_in[14];

    int B = in_sizes[0] / 105;

    static cudaStream_t s1 = nullptr, s2 = nullptr;
    static cudaEvent_t  e0 = nullptr, e1 = nullptr, e2 = nullptr;
    static bool attr_set = false;
    if (!s1) {
        cudaStreamCreateWithFlags(&s1, cudaStreamNonBlocking);
        cudaStreamCreateWithFlags(&s2, cudaStreamNonBlocking);
        cudaEventCreateWithFlags(&e0, cudaEventDisableTiming);
        cudaEventCreateWithFlags(&e1, cudaEventDisableTiming);
        cudaEventCreateWithFlags(&e2, cudaEventDisableTiming);
    }
    if (!attr_set) {
        cudaFuncSetAttribute(cnn_kernel, cudaFuncAttributeMaxDynamicSharedMemorySize,
                             CNN_SMEM_BYTES);
        attr_set = true;
    }

    prep_kernel<<<1600, 256>>>(snn_w2, nn_w2, fc_w, comb_w);
    cudaEventRecord(e0, 0);

    cudaStreamWaitEvent(s1, e0, 0);
    cnn_kernel<<<B / 16, 256, CNN_SMEM_BYTES, s1>>>(x, conv_w, conv_b, fc_b, B);
    cudaEventRecord(e1, s1);

    cudaStreamWaitEvent(s2, e0, 0);
    nn_kernel<<<B / 8, 256, 0, s2>>>(x, nn_w1, nn_b1, nn_b2, B);
    cudaEventRecord(e2, s2);

    snn_kernel<<<B, 1024>>>(x, snn_w1, snn_b1, snn_b2, B);

    cudaStreamWaitEvent(0, e1, 0);
    cudaStreamWaitEvent(0, e2, 0);
    comb_kernel<<<B / 16, 256>>>(comb_b, (float*)d_out, B);
}